// round 1
// baseline (speedup 1.0000x reference)
#include <cuda_runtime.h>
#include <cstdint>

// ---------------- problem constants ----------------
#define BATCH   32
#define NTOK    1024
#define DDIM    1024
#define MFF     4096
#define LN_EPS  1e-5f

// ---------------- scratch (no allocation allowed) ----------------
__device__ float g_q   [BATCH * NTOK];        // LN(Q)
__device__ float g_x   [BATCH * NTOK];        // A + Q
__device__ float g_h   [BATCH * NTOK];        // LN(x)
__device__ float g_hid [BATCH * MFF];         // silu(h@w1^T+b1)
__device__ float g_part[524288];              // split-K partial sums (2 MB)

#define MU_PART_OFF   0
#define SIG_PART_OFF  131072                  // 4*32*1024
#define W1_PART_OFF   0                       // reused after gauss consumed mu/sig
#define W2_PART_OFF   262144

// =====================================================================
// LayerNorm over rows of a 32x1024 matrix. mode 0: in=Q(param) -> g_q
//                                          mode 1: in=g_x      -> g_h
// =====================================================================
__global__ void ln_kernel(const float* __restrict__ in_param,
                          const float* __restrict__ gamma,
                          const float* __restrict__ beta,
                          int mode)
{
    const int row = blockIdx.x;              // 0..31
    const int tid = threadIdx.x;             // 0..255
    const float* in  = (mode == 0) ? in_param : g_x;
    float*       out = (mode == 0) ? g_q     : g_h;

    const float4* in4 = reinterpret_cast<const float4*>(in + row * NTOK);
    float4 v = in4[tid];

    float s  = v.x + v.y + v.z + v.w;
    float ss = v.x*v.x + v.y*v.y + v.z*v.z + v.w*v.w;

    #pragma unroll
    for (int o = 16; o; o >>= 1) {
        s  += __shfl_xor_sync(0xffffffffu, s,  o);
        ss += __shfl_xor_sync(0xffffffffu, ss, o);
    }
    __shared__ float sh_s[8], sh_ss[8];
    const int wid = tid >> 5, lane = tid & 31;
    if (lane == 0) { sh_s[wid] = s; sh_ss[wid] = ss; }
    __syncthreads();
    float ts = 0.f, tss = 0.f;
    #pragma unroll
    for (int i = 0; i < 8; ++i) { ts += sh_s[i]; tss += sh_ss[i]; }

    const float inv_n = 1.0f / (float)NTOK;
    const float mean  = ts * inv_n;
    const float var   = tss * inv_n - mean * mean;
    const float rs    = rsqrtf(var + LN_EPS);

    const float4 g4 = reinterpret_cast<const float4*>(gamma)[tid];
    const float4 b4 = reinterpret_cast<const float4*>(beta)[tid];
    float4 o4;
    o4.x = (v.x - mean) * rs * g4.x + b4.x;
    o4.y = (v.y - mean) * rs * g4.y + b4.y;
    o4.z = (v.z - mean) * rs * g4.z + b4.z;
    o4.w = (v.w - mean) * rs * g4.w + b4.w;
    reinterpret_cast<float4*>(out + row * NTOK)[tid] = o4;
}

// =====================================================================
// Split-K GEMM partial: C_part[split][m][j] = A[m, kOff:kOff+kps] . W[j, ...]
// A is 32 x lda row-major; W is N x ldw row-major. Tile 32(M) x 64(N),
// K-chunk 32, double-buffered smem, packed f32x2 FMA. 256 threads.
// gridDim = (N/64, nsplit, nz); z selects W0/W1 (for mu/sigma fusion).
// =====================================================================
#define GN  64
#define GKC 32

__global__ void gemm_part_kernel(const float* __restrict__ W0,
                                 const float* __restrict__ W1,
                                 int ldw, int N, int kPerSplit,
                                 int partOff, int partStrideZ, int amode)
{
    const float* __restrict__ A;
    int lda;
    if (amode == 0)      { A = g_q;   lda = NTOK; }
    else if (amode == 1) { A = g_h;   lda = NTOK; }
    else                 { A = g_hid; lda = MFF;  }

    const float* __restrict__ W = (blockIdx.z == 0) ? W0 : W1;
    float* __restrict__ P = g_part + partOff + (size_t)blockIdx.z * partStrideZ;

    const int j0    = blockIdx.x * GN;
    const int split = blockIdx.y;
    const int kOff  = split * kPerSplit;

    __shared__ __align__(16) float a_s[2][GKC][34];
    __shared__ __align__(16) float w_s[2][GKC][68];

    const int tid = threadIdx.x;
    const int tx  = tid & 31;
    const int ty  = tid >> 5;

    // load mapping: one float4 of A, two float4 of W per thread per chunk
    const int ra = tid >> 3;          // 0..31
    const int ca = tid & 7;           // 0..7

    const float* Arow = A + (size_t)ra * lda + kOff + ca * 4;
    const float* Wr0  = W + (size_t)(j0 + ra)      * ldw + kOff + ca * 4;
    const float* Wr1  = W + (size_t)(j0 + ra + 32) * ldw + kOff + ca * 4;

    const int T = kPerSplit / GKC;

    float4 fa, fw0, fw1;
    // prologue: load + store tile 0
    fa  = *reinterpret_cast<const float4*>(Arow);
    fw0 = *reinterpret_cast<const float4*>(Wr0);
    fw1 = *reinterpret_cast<const float4*>(Wr1);
    {
        const int c4 = ca * 4;
        a_s[0][c4+0][ra] = fa.x;  a_s[0][c4+1][ra] = fa.y;
        a_s[0][c4+2][ra] = fa.z;  a_s[0][c4+3][ra] = fa.w;
        w_s[0][c4+0][ra]    = fw0.x; w_s[0][c4+1][ra]    = fw0.y;
        w_s[0][c4+2][ra]    = fw0.z; w_s[0][c4+3][ra]    = fw0.w;
        w_s[0][c4+0][ra+32] = fw1.x; w_s[0][c4+1][ra+32] = fw1.y;
        w_s[0][c4+2][ra+32] = fw1.z; w_s[0][c4+3][ra+32] = fw1.w;
    }
    __syncthreads();

    unsigned long long acc00 = 0ull, acc01 = 0ull, acc10 = 0ull, acc11 = 0ull;

    for (int t = 0; t < T; ++t) {
        const int cur = t & 1;
        if (t + 1 < T) {       // prefetch next tile into registers
            fa  = *reinterpret_cast<const float4*>(Arow + (t+1) * GKC);
            fw0 = *reinterpret_cast<const float4*>(Wr0  + (t+1) * GKC);
            fw1 = *reinterpret_cast<const float4*>(Wr1  + (t+1) * GKC);
        }
        #pragma unroll
        for (int kk = 0; kk < GKC; ++kk) {
            unsigned long long a0 =
                *reinterpret_cast<const unsigned long long*>(&a_s[cur][kk][2*ty]);
            unsigned long long a1 =
                *reinterpret_cast<const unsigned long long*>(&a_s[cur][kk][2*ty + 16]);
            float w0v = w_s[cur][kk][tx];
            float w1v = w_s[cur][kk][tx + 32];
            unsigned long long wp0, wp1;
            asm("mov.b64 %0, {%1, %1};" : "=l"(wp0) : "f"(w0v));
            asm("mov.b64 %0, {%1, %1};" : "=l"(wp1) : "f"(w1v));
            asm("fma.rn.f32x2 %0, %1, %2, %0;" : "+l"(acc00) : "l"(a0), "l"(wp0));
            asm("fma.rn.f32x2 %0, %1, %2, %0;" : "+l"(acc01) : "l"(a0), "l"(wp1));
            asm("fma.rn.f32x2 %0, %1, %2, %0;" : "+l"(acc10) : "l"(a1), "l"(wp0));
            asm("fma.rn.f32x2 %0, %1, %2, %0;" : "+l"(acc11) : "l"(a1), "l"(wp1));
        }
        if (t + 1 < T) {
            const int nxt = (t + 1) & 1;
            const int c4 = ca * 4;
            a_s[nxt][c4+0][ra] = fa.x;  a_s[nxt][c4+1][ra] = fa.y;
            a_s[nxt][c4+2][ra] = fa.z;  a_s[nxt][c4+3][ra] = fa.w;
            w_s[nxt][c4+0][ra]    = fw0.x; w_s[nxt][c4+1][ra]    = fw0.y;
            w_s[nxt][c4+2][ra]    = fw0.z; w_s[nxt][c4+3][ra]    = fw0.w;
            w_s[nxt][c4+0][ra+32] = fw1.x; w_s[nxt][c4+1][ra+32] = fw1.y;
            w_s[nxt][c4+2][ra+32] = fw1.z; w_s[nxt][c4+3][ra+32] = fw1.w;
            __syncthreads();
        }
    }

    // write partials: m in {2ty,2ty+1,2ty+16,2ty+17}, n in {j0+tx, j0+tx+32}
    float l, h;
    const int m0 = 2 * ty, m1 = 2 * ty + 16;
    const int n0 = j0 + tx, n1 = j0 + tx + 32;
    const size_t base = (size_t)(split * BATCH) * N;
    asm("mov.b64 {%0, %1}, %2;" : "=f"(l), "=f"(h) : "l"(acc00));
    P[base + (size_t)m0     * N + n0] = l;  P[base + (size_t)(m0+1) * N + n0] = h;
    asm("mov.b64 {%0, %1}, %2;" : "=f"(l), "=f"(h) : "l"(acc01));
    P[base + (size_t)m0     * N + n1] = l;  P[base + (size_t)(m0+1) * N + n1] = h;
    asm("mov.b64 {%0, %1}, %2;" : "=f"(l), "=f"(h) : "l"(acc10));
    P[base + (size_t)m1     * N + n0] = l;  P[base + (size_t)(m1+1) * N + n0] = h;
    asm("mov.b64 {%0, %1}, %2;" : "=f"(l), "=f"(h) : "l"(acc11));
    P[base + (size_t)m1     * N + n1] = l;  P[base + (size_t)(m1+1) * N + n1] = h;
}

// =====================================================================
// Gaussian pseudo-attention: one warp per (b,i) row, streams K/V (256 MB).
// Also folds the mu/sigma split-K combine (tanh / coef) per row.
// x[b,i] = Q[b,i] + sum_d exp(coef*(K-mu)^2) * V
// =====================================================================
__global__ void gauss_kernel(const float* __restrict__ Kp,
                             const float* __restrict__ Vp,
                             const float* __restrict__ Qp,
                             const float* __restrict__ mu_b,
                             const float* __restrict__ sig_b)
{
    const int w    = (blockIdx.x * blockDim.x + threadIdx.x) >> 5;
    const int lane = threadIdx.x & 31;
    const int b = w >> 10;
    const int i = w & 1023;

    // combine split-K partials for mu / sigma (broadcast loads, cheap)
    float mu = mu_b[i];
    float sg = sig_b[i];
    #pragma unroll
    for (int s = 0; s < 4; ++s) {
        mu += g_part[MU_PART_OFF  + (size_t)(s * BATCH + b) * NTOK + i];
        sg += g_part[SIG_PART_OFF + (size_t)(s * BATCH + b) * NTOK + i];
    }
    mu = tanhf(mu);
    const float coef = -0.5f / (sg * sg + 1e-8f);

    const float4* K4 = reinterpret_cast<const float4*>(Kp) + (size_t)w * (DDIM / 4);
    const float4* V4 = reinterpret_cast<const float4*>(Vp) + (size_t)w * (DDIM / 4);

    float acc = 0.f;
    #pragma unroll
    for (int it = 0; it < 8; ++it) {
        const float4 k4 = K4[it * 32 + lane];
        const float4 v4 = V4[it * 32 + lane];
        float d;
        d = k4.x - mu; acc += __expf(coef * d * d) * v4.x;
        d = k4.y - mu; acc += __expf(coef * d * d) * v4.y;
        d = k4.z - mu; acc += __expf(coef * d * d) * v4.z;
        d = k4.w - mu; acc += __expf(coef * d * d) * v4.w;
    }
    #pragma unroll
    for (int o = 16; o; o >>= 1) acc += __shfl_xor_sync(0xffffffffu, acc, o);
    if (lane == 0) g_x[w] = acc + Qp[w];
}

// =====================================================================
// silu combine: g_hid = silu(sum_2 w1_parts + b1)        (32 x 4096)
// =====================================================================
__global__ void silu_combine_kernel(const float* __restrict__ b1)
{
    const int idx = blockIdx.x * blockDim.x + threadIdx.x;   // 0..131071
    const int m = idx >> 12;
    const int j = idx & 4095;
    float v = b1[j]
            + g_part[W1_PART_OFF + (size_t)(0 * BATCH + m) * MFF + j]
            + g_part[W1_PART_OFF + (size_t)(1 * BATCH + m) * MFF + j];
    g_hid[idx] = v / (1.0f + __expf(-v));
}

// =====================================================================
// final combine: out = x + b2 + sum_8 w2_parts            (32 x 1024)
// =====================================================================
__global__ void final_combine_kernel(const float* __restrict__ b2,
                                     float* __restrict__ out)
{
    const int idx = blockIdx.x * blockDim.x + threadIdx.x;   // 0..32767
    const int m = idx >> 10;
    const int j = idx & 1023;
    float s = g_x[idx] + b2[j];
    #pragma unroll
    for (int sp = 0; sp < 8; ++sp)
        s += g_part[W2_PART_OFF + (size_t)(sp * BATCH + m) * NTOK + j];
    out[idx] = s;
}

// =====================================================================
extern "C" void kernel_launch(void* const* d_in, const int* in_sizes, int n_in,
                              void* d_out, int out_size)
{
    const float* Q       = (const float*)d_in[0];
    const float* Kt      = (const float*)d_in[1];
    const float* Vt      = (const float*)d_in[2];
    const float* mu_w    = (const float*)d_in[3];
    const float* mu_b    = (const float*)d_in[4];
    const float* sigma_w = (const float*)d_in[5];
    const float* sigma_b = (const float*)d_in[6];
    const float* ffn_w1  = (const float*)d_in[7];
    const float* ffn_b1  = (const float*)d_in[8];
    const float* ffn_w2  = (const float*)d_in[9];
    const float* ffn_b2  = (const float*)d_in[10];
    const float* ln_ff_g = (const float*)d_in[11];
    const float* ln_ff_b = (const float*)d_in[12];
    const float* ln_q_g  = (const float*)d_in[13];
    const float* ln_q_b  = (const float*)d_in[14];
    float* out = (float*)d_out;

    // 1. q = LN(Q)
    ln_kernel<<<BATCH, 256>>>(Q, ln_q_g, ln_q_b, 0);

    // 2. mu & sigma partial GEMMs (z=0 -> mu_w, z=1 -> sigma_w), split-K 4
    gemm_part_kernel<<<dim3(NTOK / GN, 4, 2), 256>>>(
        mu_w, sigma_w, NTOK, NTOK, NTOK / 4,
        MU_PART_OFF, SIG_PART_OFF - MU_PART_OFF, 0);

    // 3. Gaussian stream (dominant) + mu/sigma epilogue fold, writes g_x
    gauss_kernel<<<(BATCH * NTOK) / 8, 256>>>(Kt, Vt, Q, mu_b, sigma_b);

    // 4. h = LN(x)
    ln_kernel<<<BATCH, 256>>>(nullptr, ln_ff_g, ln_ff_b, 1);

    // 5. FFN GEMM 1 partials: h @ w1^T, N=4096, split-K 2
    gemm_part_kernel<<<dim3(MFF / GN, 2, 1), 256>>>(
        ffn_w1, ffn_w1, NTOK, MFF, NTOK / 2,
        W1_PART_OFF, 0, 1);

    // 6. silu + bias combine -> g_hid
    silu_combine_kernel<<<(BATCH * MFF) / 256, 256>>>(ffn_b1);

    // 7. FFN GEMM 2 partials: hid @ w2^T, N=1024, split-K 8
    gemm_part_kernel<<<dim3(NTOK / GN, 8, 1), 256>>>(
        ffn_w2, ffn_w2, MFF, NTOK, MFF / 8,
        W2_PART_OFF, 0, 2);

    // 8. out = x + b2 + sum parts
    final_combine_kernel<<<(BATCH * NTOK) / 256, 256>>>(ffn_b2, out);
}